// round 1
// baseline (speedup 1.0000x reference)
#include <cuda_runtime.h>
#include <math.h>

#define HH 256
#define WW 256
#define HWTOT 65536
#define BB 4

// ---------------- device scratch (no allocation allowed) ----------------
__device__ float g_q1[67108864];   // (4,256,256,256) conv1 output (relu'd)
__device__ float g_q2[67108864];   // (4,256,256,256) conv2 output (relu'd)
__device__ float g_w3t[65536];     // w3 transposed: [ci][co]
__device__ float g_M2t[256 * 16];  // M2t[ci][k] = sum_co mu[k][co]*w3[co][ci]
__device__ float g_c0[16];         // mu_k . b3
__device__ float g_mu2[16];        // |mu_k|^2

// ---------------- prep: transposes + head constants ----------------
__global__ void prep_kernel(const float* __restrict__ w3,
                            const float* __restrict__ b3,
                            const float* __restrict__ mu) {
    const int tid = threadIdx.x;
    // transpose w3 (256x256): g_w3t[ci*256+co] = w3[co*256+ci]
    for (int i = tid; i < 65536; i += 256) {
        int co = i >> 8, ci = i & 255;
        g_w3t[ci * 256 + co] = w3[i];
    }
    // M2t[ci][k]
    for (int p = tid; p < 4096; p += 256) {
        int ci = p >> 4, k = p & 15;
        float s = 0.f;
        for (int co = 0; co < 256; ++co)
            s = fmaf(mu[k * 256 + co], w3[co * 256 + ci], s);
        g_M2t[ci * 16 + k] = s;
    }
    if (tid < 16) {
        float s = 0.f, m2 = 0.f;
        for (int c = 0; c < 256; ++c) {
            float mv = mu[tid * 256 + c];
            s  = fmaf(mv, b3[c], s);
            m2 = fmaf(mv, mv, m2);
        }
        g_c0[tid]  = s;
        g_mu2[tid] = m2;
    }
}

// ---------------- conv 3x3 replicate-pad + bias + relu ----------------
// grid: (W/32=8, (H/32)*B=32, 256/16=16), block 256 threads
// thread: 2x2 pixels x 16 cout accumulators
template <int CIN>
__global__ __launch_bounds__(256, 2) void conv3x3_relu_kernel(
    const float* __restrict__ in,   // [B][CIN][H][W]
    const float* __restrict__ wgt,  // [256][CIN][3][3]
    const float* __restrict__ bias, // [256]
    float* __restrict__ out)        // [B][256][H][W]
{
    __shared__ __align__(16) float xs[34][36];
    __shared__ __align__(16) float ws[9][16];

    const int tid = threadIdx.x;
    const int tx = tid & 15, ty = tid >> 4;
    const int wt = blockIdx.x;
    const int ht = blockIdx.y & 7;
    const int b  = blockIdx.y >> 3;
    const int cog = blockIdx.z;
    const int h0 = ht * 32, w0 = wt * 32;
    const float* inb = in + (size_t)b * CIN * HWTOT;

    float acc[2][2][16];
#pragma unroll
    for (int pi = 0; pi < 2; ++pi)
#pragma unroll
        for (int pj = 0; pj < 2; ++pj)
#pragma unroll
            for (int c = 0; c < 16; ++c) acc[pi][pj][c] = 0.f;

    const int pr = ty * 2, pc = tx * 2;

    for (int ci = 0; ci < CIN; ++ci) {
        __syncthreads();
        if (tid < 144) {
            int t = tid % 9, co = tid / 9;
            ws[t][co] = wgt[((cog * 16 + co) * CIN + ci) * 9 + t];
        }
        const float* inc = inb + (size_t)ci * HWTOT;
#pragma unroll
        for (int k = 0; k < 5; ++k) {
            int idx = tid + k * 256;
            if (idx < 34 * 34) {
                int r = idx / 34, c = idx - r * 34;
                int gh = min(max(h0 + r - 1, 0), HH - 1);
                int gw = min(max(w0 + c - 1, 0), WW - 1);
                xs[r][c] = inc[gh * WW + gw];
            }
        }
        __syncthreads();

        float xr[4][4];
#pragma unroll
        for (int i = 0; i < 4; ++i)
#pragma unroll
            for (int j = 0; j < 2; ++j) {
                float2 v = *(const float2*)&xs[pr + i][pc + 2 * j];
                xr[i][2 * j] = v.x;
                xr[i][2 * j + 1] = v.y;
            }

#pragma unroll
        for (int cg = 0; cg < 4; ++cg) {
            float4 wv[9];
#pragma unroll
            for (int t = 0; t < 9; ++t)
                wv[t] = *(const float4*)&ws[t][cg * 4];
#pragma unroll
            for (int t = 0; t < 9; ++t) {
                const int dr = t / 3, dc = t % 3;
#pragma unroll
                for (int pi = 0; pi < 2; ++pi)
#pragma unroll
                    for (int pj = 0; pj < 2; ++pj) {
                        float xv = xr[pi + dr][pj + dc];
                        acc[pi][pj][cg * 4 + 0] = fmaf(xv, wv[t].x, acc[pi][pj][cg * 4 + 0]);
                        acc[pi][pj][cg * 4 + 1] = fmaf(xv, wv[t].y, acc[pi][pj][cg * 4 + 1]);
                        acc[pi][pj][cg * 4 + 2] = fmaf(xv, wv[t].z, acc[pi][pj][cg * 4 + 2]);
                        acc[pi][pj][cg * 4 + 3] = fmaf(xv, wv[t].w, acc[pi][pj][cg * 4 + 3]);
                    }
            }
        }
    }

#pragma unroll
    for (int c = 0; c < 16; ++c) {
        float bv = bias[cog * 16 + c];
#pragma unroll
        for (int pi = 0; pi < 2; ++pi)
#pragma unroll
            for (int pj = 0; pj < 2; ++pj) {
                float v = fmaxf(acc[pi][pj][c] + bv, 0.f);
                out[(((size_t)(b * 256 + cog * 16 + c)) * HH + (h0 + pr + pi)) * WW +
                    (w0 + pc + pj)] = v;
            }
    }
}

// ---------------- fused 1x1 conv + cluster softmax head ----------------
// grid: (HW/64=1024, B=4), block 256 threads.
// GEMM: q[256co][64px] = W3 . q2, thread tile 8px x 8co (split-float4 lanes).
// cross_k folded in via M2t during the same reduction; softmax via warp shfl.
__global__ __launch_bounds__(256, 2) void head_kernel(
    const float* __restrict__ b3,
    const float* __restrict__ label,
    float* __restrict__ out)
{
    __shared__ __align__(16) float ws[16][256];
    __shared__ __align__(16) float bs[16][64];
    __shared__ __align__(16) float m2s[256][16];
    __shared__ float mu2s[16], c0s[16], labs[16];

    const int tid = threadIdx.x;
    const int tx = tid & 31, ty = tid >> 5;
    const int hw0 = blockIdx.x * 64;
    const int b = blockIdx.y;
    const float* q2b = g_q2 + (size_t)b * 256 * HWTOT;
    const int kk = tx & 15;

    for (int i = tid; i < 4096; i += 256) m2s[i >> 4][i & 15] = g_M2t[i];
    if (tid < 16) {
        mu2s[tid] = g_mu2[tid];
        c0s[tid]  = g_c0[tid];
        labs[tid] = label[tid];
    }

    float acc[8][8];
    float crp[8];
#pragma unroll
    for (int pi = 0; pi < 8; ++pi) {
        crp[pi] = 0.f;
#pragma unroll
        for (int ci = 0; ci < 8; ++ci) acc[pi][ci] = 0.f;
    }

    for (int c0 = 0; c0 < 256; c0 += 16) {
        __syncthreads();
#pragma unroll
        for (int m = 0; m < 4; ++m) {
            int v = tid + m * 256;
            int s = v >> 6;
            int co = (v & 63) << 2;
            *(float4*)&ws[s][co] = *(const float4*)&g_w3t[(c0 + s) * 256 + co];
        }
        {
            int s = tid >> 4, p = (tid & 15) << 2;
            *(float4*)&bs[s][p] =
                *(const float4*)&q2b[(size_t)(c0 + s) * HWTOT + hw0 + p];
        }
        __syncthreads();
#pragma unroll
        for (int s = 0; s < 16; ++s) {
            float4 a0 = *(const float4*)&bs[s][ty * 4];
            float4 a1 = *(const float4*)&bs[s][32 + ty * 4];
            float4 w0v = *(const float4*)&ws[s][tx * 4];
            float4 w1v = *(const float4*)&ws[s][128 + tx * 4];
            float av[8] = {a0.x, a0.y, a0.z, a0.w, a1.x, a1.y, a1.z, a1.w};
            float wv[8] = {w0v.x, w0v.y, w0v.z, w0v.w, w1v.x, w1v.y, w1v.z, w1v.w};
            float m2v = m2s[c0 + s][kk];
#pragma unroll
            for (int pi = 0; pi < 8; ++pi) {
#pragma unroll
                for (int ci = 0; ci < 8; ++ci)
                    acc[pi][ci] = fmaf(av[pi], wv[ci], acc[pi][ci]);
                crp[pi] = fmaf(av[pi], m2v, crp[pi]);
            }
        }
    }

    float4 bb0 = *(const float4*)&b3[tx * 4];
    float4 bb1 = *(const float4*)&b3[128 + tx * 4];
    float bc[8] = {bb0.x, bb0.y, bb0.z, bb0.w, bb1.x, bb1.y, bb1.z, bb1.w};

#pragma unroll
    for (int pi = 0; pi < 8; ++pi) {
        float s2 = 0.f;
#pragma unroll
        for (int ci = 0; ci < 8; ++ci) {
            float q = acc[pi][ci] + bc[ci];
            s2 = fmaf(q, q, s2);
        }
#pragma unroll
        for (int off = 16; off; off >>= 1)
            s2 += __shfl_xor_sync(0xffffffffu, s2, off);

        float cr = crp[pi] + c0s[kk];
        float logit = 2.f * cr - s2 - mu2s[kk];

        float mx = logit;
#pragma unroll
        for (int off = 8; off; off >>= 1)
            mx = fmaxf(mx, __shfl_xor_sync(0xffffffffu, mx, off));
        float e = __expf(logit - mx);
        float se = e, sl = e * labs[kk];
#pragma unroll
        for (int off = 8; off; off >>= 1) {
            se += __shfl_xor_sync(0xffffffffu, se, off);
            sl += __shfl_xor_sync(0xffffffffu, sl, off);
        }
        if (tx == 0) {
            int p = (pi < 4) ? (ty * 4 + pi) : (32 + ty * 4 + (pi - 4));
            out[(size_t)b * HWTOT + hw0 + p] = sl / se;
        }
    }
}

// ---------------- launch ----------------
extern "C" void kernel_launch(void* const* d_in, const int* in_sizes, int n_in,
                              void* d_out, int out_size) {
    const float* x     = (const float*)d_in[0];
    const float* w1    = (const float*)d_in[1];
    const float* b1    = (const float*)d_in[2];
    const float* w2    = (const float*)d_in[3];
    const float* b2    = (const float*)d_in[4];
    const float* w3    = (const float*)d_in[5];
    const float* b3    = (const float*)d_in[6];
    const float* mu    = (const float*)d_in[7];
    const float* label = (const float*)d_in[8];
    float* out = (float*)d_out;

    prep_kernel<<<1, 256>>>(w3, b3, mu);

    float* q1;  cudaGetSymbolAddress((void**)&q1, g_q1);
    float* q2;  cudaGetSymbolAddress((void**)&q2, g_q2);

    dim3 cgrid(8, 32, 16);
    conv3x3_relu_kernel<64><<<cgrid, 256>>>(x, w1, b1, q1);
    conv3x3_relu_kernel<256><<<cgrid, 256>>>(q1, w2, b2, q2);

    head_kernel<<<dim3(1024, 4), 256>>>(b3, label, out);
}

// round 3
// speedup vs baseline: 1.7618x; 1.7618x over previous
#include <cuda_runtime.h>
#include <cuda_bf16.h>
#include <cstdint>
#include <math.h>

#define HH 256
#define WW 256
#define HWTOT 65536

// ===================== device scratch =====================
__device__ __align__(256) __nv_bfloat16 g_xp[50724864];    // 3 * 4*256*258*64   [s][b][h][w0..257][ci]
__device__ __align__(256) __nv_bfloat16 g_q1p[202899456];  // 3 * 4*256*258*256
__device__ __align__(256) float         g_q2[67108864];    // planar (4,256,256,256)
__device__ __align__(256) __nv_bfloat16 g_w1s[442368];     // 3 * 9*256*64   [s][chunk][co][ci64]
__device__ __align__(256) __nv_bfloat16 g_w2s[1769472];    // 3 * 36*256*64
__device__ float g_w3t[65536];
__device__ float g_M2t[256 * 16];
__device__ float g_c0[16];
__device__ float g_mu2[16];

// ===================== helpers =====================
__device__ __forceinline__ uint32_t smem_u32(const void* p) {
    uint32_t a;
    asm("{ .reg .u64 t; cvta.to.shared.u64 t, %1; cvt.u32.u64 %0, t; }" : "=r"(a) : "l"(p));
    return a;
}
__device__ __forceinline__ uint32_t swz128(uint32_t o) { return o ^ ((o >> 3) & 0x70); }

__device__ __forceinline__ void cp_async16(uint32_t dst, const void* src) {
    asm volatile("cp.async.cg.shared.global [%0], [%1], 16;" :: "r"(dst), "l"(src) : "memory");
}
#define CP_COMMIT() asm volatile("cp.async.commit_group;" ::: "memory")
#define CP_WAIT(n)  asm volatile("cp.async.wait_group %0;" :: "n"(n) : "memory")

#define LDSM_X4(r0, r1, r2, r3, addr) \
    asm volatile("ldmatrix.sync.aligned.m8n8.x4.shared.b16 {%0,%1,%2,%3}, [%4];" \
                 : "=r"(r0), "=r"(r1), "=r"(r2), "=r"(r3) : "r"(addr))

#define MMA16816(d, a, b0, b1) \
    asm volatile("mma.sync.aligned.m16n8k16.row.col.f32.bf16.bf16.f32 " \
                 "{%0,%1,%2,%3}, {%4,%5,%6,%7}, {%8,%9}, {%0,%1,%2,%3};" \
                 : "+f"((d)[0]), "+f"((d)[1]), "+f"((d)[2]), "+f"((d)[3]) \
                 : "r"((a)[0]), "r"((a)[1]), "r"((a)[2]), "r"((a)[3]), "r"(b0), "r"(b1))

__device__ __forceinline__ void split3(float v, __nv_bfloat16& a0, __nv_bfloat16& a1,
                                       __nv_bfloat16& a2) {
    a0 = __float2bfloat16(v);
    float r = v - __bfloat162float(a0);
    a1 = __float2bfloat16(r);
    float r2 = r - __bfloat162float(a1);
    a2 = __float2bfloat16(r2);
}
__device__ __forceinline__ uint32_t packbf(__nv_bfloat16 lo, __nv_bfloat16 hi) {
    unsigned short a = *reinterpret_cast<unsigned short*>(&lo);
    unsigned short b = *reinterpret_cast<unsigned short*>(&hi);
    return (uint32_t)a | ((uint32_t)b << 16);
}

// ===================== prep kernels =====================
__global__ void prep_head(const float* __restrict__ w3, const float* __restrict__ b3,
                          const float* __restrict__ mu) {
    const int tid = threadIdx.x;
    for (int i = tid; i < 65536; i += 256) {
        int co = i >> 8, ci = i & 255;
        g_w3t[ci * 256 + co] = w3[i];
    }
    for (int p = tid; p < 4096; p += 256) {
        int ci = p >> 4, k = p & 15;
        float s = 0.f;
        for (int co = 0; co < 256; ++co) s = fmaf(mu[k * 256 + co], w3[co * 256 + ci], s);
        g_M2t[ci * 16 + k] = s;
    }
    if (tid < 16) {
        float s = 0.f, m2 = 0.f;
        for (int c = 0; c < 256; ++c) {
            float mv = mu[tid * 256 + c];
            s = fmaf(mv, b3[c], s);
            m2 = fmaf(mv, mv, m2);
        }
        g_c0[tid] = s;
        g_mu2[tid] = m2;
    }
}

__global__ void prep_x(const float* __restrict__ x) {
    const int h = blockIdx.x, b = blockIdx.y, tid = threadIdx.x;
    const size_t XPLANE = 16908288;
    for (int idx = tid; idx < 258 * 64; idx += 256) {
        int w = idx >> 6, ci = idx & 63;
        int wsrc = min(max(w - 1, 0), WW - 1);
        float v = x[(((size_t)b * 64 + ci) * HH + h) * WW + wsrc];
        __nv_bfloat16 s0, s1, s2;
        split3(v, s0, s1, s2);
        size_t base = (((size_t)b * 256 + h) * 258 + w) * 64 + ci;
        g_xp[base] = s0;
        g_xp[base + XPLANE] = s1;
        g_xp[base + 2 * XPLANE] = s2;
    }
}

template <int CIN>
__global__ void prep_w(const float* __restrict__ w, __nv_bfloat16* __restrict__ dst) {
    const int NCC = CIN / 64;
    const size_t WPLANE = (size_t)256 * CIN * 9;
    int gid = blockIdx.x * 256 + threadIdx.x;
    if (gid >= (int)WPLANE) return;
    int tap = gid % 9, r = gid / 9;
    int ci = r % CIN, co = r / CIN;
    int dr = tap / 3, dc = tap % 3;
    int cic = ci >> 6, cj = ci & 63;
    int chunk = (dr * NCC + cic) * 3 + dc;
    size_t di = ((size_t)chunk * 256 + co) * 64 + cj;
    __nv_bfloat16 s0, s1, s2;
    split3(w[gid], s0, s1, s2);
    dst[di] = s0;
    dst[di + WPLANE] = s1;
    dst[di + 2 * WPLANE] = s2;
}

// ===================== conv via mma.sync =====================
// grid (4 = 2 pxHalf x 2 coHalf, 256 h, 4 b), 256 threads (8 warps: 4M x 2N).
// CTA tile: 128 px x 128 co.  K chunks of 64 ci x 1 tap; 3-term bf16 split, 6 products.
template <int CIN, bool SPLIT_OUT>
__global__ __launch_bounds__(256) void conv_mma(
    const __nv_bfloat16* __restrict__ xp,   // [s][b][h][258][CIN]
    const __nv_bfloat16* __restrict__ wsp,  // [s][chunk][256][64]
    const float* __restrict__ bias,
    __nv_bfloat16* __restrict__ out_split,  // [s][b][h][258][256]
    float* __restrict__ out_planar)         // [b][co][h][w]
{
    constexpr int NCC = CIN / 64;
    constexpr int NCH = 9 * NCC;
    const size_t IPLANE = (size_t)4 * 256 * 258 * CIN;
    const size_t WPLANE = (size_t)NCH * 16384;
    const size_t OPLANE = (size_t)4 * 256 * 258 * 256;
    constexpr uint32_t BUFB = 98304;  // 48KB A + 48KB B per buffer

    extern __shared__ char smem_raw[];
    const uint32_t abase = (smem_u32(smem_raw) + 1023u) & ~1023u;

    const int tid = threadIdx.x;
    const int wid = tid >> 5, lane = tid & 31;
    const int warpM = wid & 3, warpN = wid >> 2;
    const int h = blockIdx.y, b = blockIdx.z;
    const int pxBase = (blockIdx.x & 1) * 128;
    const int coBase = (blockIdx.x >> 1) * 128;

    // ---- staging lambda: one K-chunk (A tile + B tile, 3 planes each) ----
    auto stage = [&](int chunk, int buf) {
        int dc = chunk % 3;
        int rem = chunk / 3;
        int cic = rem % NCC;
        int dr = rem / NCC;
        int hr = min(max(h + dr - 1, 0), HH - 1);
        const __nv_bfloat16* xrow = xp + (((size_t)b * 256 + hr) * 258 + pxBase + dc) * CIN + cic * 64;
        uint32_t aoff = abase + buf * BUFB;
        uint32_t boff = aoff + 49152;
#pragma unroll
        for (int t = 0; t < 12; ++t) {
            int idx = tid + (t << 8);
            int plane = idx >> 10, r = idx & 1023;
            int px = r >> 3, seg = r & 7;
            const void* src = xrow + (size_t)plane * IPLANE + (size_t)px * CIN + seg * 8;
            cp_async16(aoff + plane * 16384 + swz128((px << 7) | (seg << 4)), src);
        }
        const __nv_bfloat16* wrow = wsp + ((size_t)chunk * 256 + coBase) * 64;
#pragma unroll
        for (int t = 0; t < 12; ++t) {
            int idx = tid + (t << 8);
            int plane = idx >> 10, r = idx & 1023;
            int co = r >> 3, seg = r & 7;
            const void* src = wrow + (size_t)plane * WPLANE + (size_t)co * 64 + seg * 8;
            cp_async16(boff + plane * 16384 + swz128((co << 7) | (seg << 4)), src);
        }
        CP_COMMIT();
    };

    float acc[2][8][4];
#pragma unroll
    for (int mt = 0; mt < 2; ++mt)
#pragma unroll
        for (int nt = 0; nt < 8; ++nt)
#pragma unroll
            for (int e = 0; e < 4; ++e) acc[mt][nt][e] = 0.f;

    // per-lane ldmatrix address components
    const uint32_t rA = lane & 15, cA = (lane >> 4) << 4;
    const uint32_t rB = (lane & 7) | ((lane >> 4) << 3), cB = ((lane >> 3) & 1) << 4;

    const int SA[6] = {0, 0, 1, 1, 0, 2};
    const int SB[6] = {0, 1, 0, 1, 2, 0};

    stage(0, 0);
    if (NCH > 1) stage(1, 1);

    for (int c = 0; c < NCH; ++c) {
        if (c + 1 < NCH) { CP_WAIT(1); } else { CP_WAIT(0); }
        __syncthreads();

        const int buf = c & 1;
        const uint32_t aB = abase + buf * BUFB;
        const uint32_t bB = aB + 49152;

        for (int ks = 0; ks < 4; ++ks) {
            uint32_t af[3][2][4];
#pragma unroll
            for (int plane = 0; plane < 3; ++plane)
#pragma unroll
                for (int mt = 0; mt < 2; ++mt) {
                    uint32_t row = warpM * 32 + mt * 16 + rA;
                    uint32_t addr = aB + plane * 16384 + swz128((row << 7) + ks * 32 + cA);
                    LDSM_X4(af[plane][mt][0], af[plane][mt][1], af[plane][mt][2],
                            af[plane][mt][3], addr);
                }
#pragma unroll
            for (int np = 0; np < 4; ++np) {
                uint32_t bfr[3][4];
#pragma unroll
                for (int plane = 0; plane < 3; ++plane) {
                    uint32_t row = warpN * 64 + np * 16 + rB;
                    uint32_t addr = bB + plane * 16384 + swz128((row << 7) + ks * 32 + cB);
                    LDSM_X4(bfr[plane][0], bfr[plane][1], bfr[plane][2], bfr[plane][3], addr);
                }
#pragma unroll
                for (int t = 0; t < 6; ++t) {
                    const int sa = SA[t], sb = SB[t];
#pragma unroll
                    for (int mt = 0; mt < 2; ++mt) {
                        MMA16816(acc[mt][2 * np], af[sa][mt], bfr[sb][0], bfr[sb][1]);
                        MMA16816(acc[mt][2 * np + 1], af[sa][mt], bfr[sb][2], bfr[sb][3]);
                    }
                }
            }
        }
        __syncthreads();
        if (c + 2 < NCH) stage(c + 2, buf);
    }

    // ---- epilogue ----
    float bv0[8], bv1[8];
#pragma unroll
    for (int nt = 0; nt < 8; ++nt) {
        int c0 = coBase + warpN * 64 + nt * 8 + (lane & 3) * 2;
        bv0[nt] = __ldg(bias + c0);
        bv1[nt] = __ldg(bias + c0 + 1);
    }

#pragma unroll
    for (int mt = 0; mt < 2; ++mt) {
#pragma unroll
        for (int nt = 0; nt < 8; ++nt) {
            int px0 = pxBase + warpM * 32 + mt * 16 + (lane >> 2);
            int c0 = coBase + warpN * 64 + nt * 8 + (lane & 3) * 2;
#pragma unroll
            for (int half = 0; half < 2; ++half) {
                int px = px0 + half * 8;
                float v0 = fmaxf(acc[mt][nt][2 * half] + bv0[nt], 0.f);
                float v1 = fmaxf(acc[mt][nt][2 * half + 1] + bv1[nt], 0.f);
                if (SPLIT_OUT) {
                    __nv_bfloat16 a0, a1, a2, d0, d1, d2;
                    split3(v0, a0, a1, a2);
                    split3(v1, d0, d1, d2);
                    uint32_t p0 = packbf(a0, d0), p1 = packbf(a1, d1), p2 = packbf(a2, d2);
                    size_t base = (((size_t)b * 256 + h) * 258 + px + 1) * 256 + c0;
                    *reinterpret_cast<uint32_t*>(out_split + base) = p0;
                    *reinterpret_cast<uint32_t*>(out_split + OPLANE + base) = p1;
                    *reinterpret_cast<uint32_t*>(out_split + 2 * OPLANE + base) = p2;
                    if (px == 0 || px == 255) {
                        size_t hb = (((size_t)b * 256 + h) * 258 + (px == 0 ? 0 : 257)) * 256 + c0;
                        *reinterpret_cast<uint32_t*>(out_split + hb) = p0;
                        *reinterpret_cast<uint32_t*>(out_split + OPLANE + hb) = p1;
                        *reinterpret_cast<uint32_t*>(out_split + 2 * OPLANE + hb) = p2;
                    }
                } else {
                    size_t o0 = ((size_t)b * 256 + c0) * HWTOT + h * WW + px;
                    out_planar[o0] = v0;
                    out_planar[o0 + HWTOT] = v1;
                }
            }
        }
    }
}

// ===================== fused 1x1 conv + cluster softmax head =====================
__global__ __launch_bounds__(256, 2) void head_kernel(
    const float* __restrict__ b3, const float* __restrict__ label, float* __restrict__ out)
{
    __shared__ __align__(16) float ws[16][256];
    __shared__ __align__(16) float bs[16][64];
    __shared__ __align__(16) float m2s[256][16];
    __shared__ float mu2s[16], c0s[16], labs[16];

    const int tid = threadIdx.x;
    const int tx = tid & 31, ty = tid >> 5;
    const int hw0 = blockIdx.x * 64;
    const int b = blockIdx.y;
    const float* q2b = g_q2 + (size_t)b * 256 * HWTOT;
    const int kk = tx & 15;

    for (int i = tid; i < 4096; i += 256) m2s[i >> 4][i & 15] = g_M2t[i];
    if (tid < 16) {
        mu2s[tid] = g_mu2[tid];
        c0s[tid] = g_c0[tid];
        labs[tid] = label[tid];
    }

    float acc[8][8];
    float crp[8];
#pragma unroll
    for (int pi = 0; pi < 8; ++pi) {
        crp[pi] = 0.f;
#pragma unroll
        for (int ci = 0; ci < 8; ++ci) acc[pi][ci] = 0.f;
    }

    for (int c0 = 0; c0 < 256; c0 += 16) {
        __syncthreads();
#pragma unroll
        for (int m = 0; m < 4; ++m) {
            int v = tid + m * 256;
            int s = v >> 6;
            int co = (v & 63) << 2;
            *(float4*)&ws[s][co] = *(const float4*)&g_w3t[(c0 + s) * 256 + co];
        }
        {
            int s = tid >> 4, p = (tid & 15) << 2;
            *(float4*)&bs[s][p] = *(const float4*)&q2b[(size_t)(c0 + s) * HWTOT + hw0 + p];
        }
        __syncthreads();
#pragma unroll
        for (int s = 0; s < 16; ++s) {
            float4 a0 = *(const float4*)&bs[s][ty * 4];
            float4 a1 = *(const float4*)&bs[s][32 + ty * 4];
            float4 w0v = *(const float4*)&ws[s][tx * 4];
            float4 w1v = *(const float4*)&ws[s][128 + tx * 4];
            float av[8] = {a0.x, a0.y, a0.z, a0.w, a1.x, a1.y, a1.z, a1.w};
            float wv[8] = {w0v.x, w0v.y, w0v.z, w0v.w, w1v.x, w1v.y, w1v.z, w1v.w};
            float m2v = m2s[c0 + s][kk];
#pragma unroll
            for (int pi = 0; pi < 8; ++pi) {
#pragma unroll
                for (int ci = 0; ci < 8; ++ci) acc[pi][ci] = fmaf(av[pi], wv[ci], acc[pi][ci]);
                crp[pi] = fmaf(av[pi], m2v, crp[pi]);
            }
        }
    }

    float4 bb0 = *(const float4*)&b3[tx * 4];
    float4 bb1 = *(const float4*)&b3[128 + tx * 4];
    float bc[8] = {bb0.x, bb0.y, bb0.z, bb0.w, bb1.x, bb1.y, bb1.z, bb1.w};

#pragma unroll
    for (int pi = 0; pi < 8; ++pi) {
        float s2 = 0.f;
#pragma unroll
        for (int ci = 0; ci < 8; ++ci) {
            float q = acc[pi][ci] + bc[ci];
            s2 = fmaf(q, q, s2);
        }
#pragma unroll
        for (int off = 16; off; off >>= 1) s2 += __shfl_xor_sync(0xffffffffu, s2, off);

        float cr = crp[pi] + c0s[kk];
        float logit = 2.f * cr - s2 - mu2s[kk];

        float mx = logit;
#pragma unroll
        for (int off = 8; off; off >>= 1)
            mx = fmaxf(mx, __shfl_xor_sync(0xffffffffu, mx, off));
        float e = __expf(logit - mx);
        float se = e, sl = e * labs[kk];
#pragma unroll
        for (int off = 8; off; off >>= 1) {
            se += __shfl_xor_sync(0xffffffffu, se, off);
            sl += __shfl_xor_sync(0xffffffffu, sl, off);
        }
        if (tx == 0) {
            int p = (pi < 4) ? (ty * 4 + pi) : (32 + ty * 4 + (pi - 4));
            out[(size_t)b * HWTOT + hw0 + p] = sl / se;
        }
    }
}

// ===================== launch =====================
extern "C" void kernel_launch(void* const* d_in, const int* in_sizes, int n_in,
                              void* d_out, int out_size) {
    const float* x = (const float*)d_in[0];
    const float* w1 = (const float*)d_in[1];
    const float* b1 = (const float*)d_in[2];
    const float* w2 = (const float*)d_in[3];
    const float* b2 = (const float*)d_in[4];
    const float* w3 = (const float*)d_in[5];
    const float* b3 = (const float*)d_in[6];
    const float* mu = (const float*)d_in[7];
    const float* label = (const float*)d_in[8];
    float* out = (float*)d_out;

    __nv_bfloat16 *xp, *q1p, *w1s, *w2s;
    float* q2;
    cudaGetSymbolAddress((void**)&xp, g_xp);
    cudaGetSymbolAddress((void**)&q1p, g_q1p);
    cudaGetSymbolAddress((void**)&q2, g_q2);
    cudaGetSymbolAddress((void**)&w1s, g_w1s);
    cudaGetSymbolAddress((void**)&w2s, g_w2s);

    const int SMEM_BYTES = 2 * 98304 + 1024;
    cudaFuncSetAttribute(conv_mma<64, true>, cudaFuncAttributeMaxDynamicSharedMemorySize,
                         SMEM_BYTES);
    cudaFuncSetAttribute(conv_mma<256, false>, cudaFuncAttributeMaxDynamicSharedMemorySize,
                         SMEM_BYTES);

    prep_head<<<1, 256>>>(w3, b3, mu);
    prep_x<<<dim3(256, 4), 256>>>(x);
    prep_w<64><<<576, 256>>>(w1, w1s);
    prep_w<256><<<2304, 256>>>(w2, w2s);

    dim3 cgrid(4, 256, 4);
    conv_mma<64, true><<<cgrid, 256, SMEM_BYTES>>>(xp, w1s, b1, q1p, nullptr);
    conv_mma<256, false><<<cgrid, 256, SMEM_BYTES>>>(q1p, w2s, b2, nullptr, q2);

    head_kernel<<<dim3(1024, 4), 256>>>(b3, label, out);
}

// round 4
// speedup vs baseline: 2.7540x; 1.5632x over previous
#include <cuda_runtime.h>
#include <cuda_fp16.h>
#include <cstdint>
#include <math.h>

#define HH 256
#define WW 256
#define HWTOT 65536

// ===================== device scratch =====================
__device__ __align__(256) __half g_xp[33816576];    // 2 * 4*256*258*64   [s][b][h][w0..257][ci]
__device__ __align__(256) __half g_q1p[135266304];  // 2 * 4*256*258*256
__device__ __align__(256) float  g_q2[67108864];    // planar (4,256,256,256)
__device__ __align__(256) __half g_w1s[294912];     // 2 * 9*256*64   [s][chunk][co][ci64]
__device__ __align__(256) __half g_w2s[1179648];    // 2 * 36*256*64
__device__ float g_w3t[65536];
__device__ float g_M2t[256 * 16];
__device__ float g_c0[16];
__device__ float g_mu2[16];

// ===================== helpers =====================
__device__ __forceinline__ uint32_t smem_u32(const void* p) {
    uint32_t a;
    asm("{ .reg .u64 t; cvta.to.shared.u64 t, %1; cvt.u32.u64 %0, t; }" : "=r"(a) : "l"(p));
    return a;
}
__device__ __forceinline__ uint32_t swz128(uint32_t o) { return o ^ ((o >> 3) & 0x70); }

__device__ __forceinline__ void cp_async16(uint32_t dst, const void* src) {
    asm volatile("cp.async.cg.shared.global [%0], [%1], 16;" :: "r"(dst), "l"(src) : "memory");
}
#define CP_COMMIT() asm volatile("cp.async.commit_group;" ::: "memory")
#define CP_WAIT(n)  asm volatile("cp.async.wait_group %0;" :: "n"(n) : "memory")

#define LDSM_X4(r0, r1, r2, r3, addr) \
    asm volatile("ldmatrix.sync.aligned.m8n8.x4.shared.b16 {%0,%1,%2,%3}, [%4];" \
                 : "=r"(r0), "=r"(r1), "=r"(r2), "=r"(r3) : "r"(addr))

#define MMA16816(d, a, b0, b1) \
    asm volatile("mma.sync.aligned.m16n8k16.row.col.f32.f16.f16.f32 " \
                 "{%0,%1,%2,%3}, {%4,%5,%6,%7}, {%8,%9}, {%0,%1,%2,%3};" \
                 : "+f"((d)[0]), "+f"((d)[1]), "+f"((d)[2]), "+f"((d)[3]) \
                 : "r"((a)[0]), "r"((a)[1]), "r"((a)[2]), "r"((a)[3]), "r"(b0), "r"(b1))

__device__ __forceinline__ void split2(float v, __half& h0, __half& h1) {
    h0 = __float2half_rn(v);
    float r = v - __half2float(h0);
    h1 = __float2half_rn(r);
}
__device__ __forceinline__ uint32_t packh(__half lo, __half hi) {
    unsigned short a = *reinterpret_cast<unsigned short*>(&lo);
    unsigned short b = *reinterpret_cast<unsigned short*>(&hi);
    return (uint32_t)a | ((uint32_t)b << 16);
}

// ===================== prep kernels =====================
__global__ void prep_head(const float* __restrict__ w3, const float* __restrict__ b3,
                          const float* __restrict__ mu) {
    const int tid = threadIdx.x;
    for (int i = tid; i < 65536; i += 256) {
        int co = i >> 8, ci = i & 255;
        g_w3t[ci * 256 + co] = w3[i];
    }
    for (int p = tid; p < 4096; p += 256) {
        int ci = p >> 4, k = p & 15;
        float s = 0.f;
        for (int co = 0; co < 256; ++co) s = fmaf(mu[k * 256 + co], w3[co * 256 + ci], s);
        g_M2t[ci * 16 + k] = s;
    }
    if (tid < 16) {
        float s = 0.f, m2 = 0.f;
        for (int c = 0; c < 256; ++c) {
            float mv = mu[tid * 256 + c];
            s = fmaf(mv, b3[c], s);
            m2 = fmaf(mv, mv, m2);
        }
        g_c0[tid] = s;
        g_mu2[tid] = m2;
    }
}

__global__ void prep_x(const float* __restrict__ x) {
    const int h = blockIdx.x, b = blockIdx.y, tid = threadIdx.x;
    const size_t XPLANE = 16908288;  // 4*256*258*64
    for (int idx = tid; idx < 258 * 64; idx += 256) {
        int w = idx >> 6, ci = idx & 63;
        int wsrc = min(max(w - 1, 0), WW - 1);
        float v = x[(((size_t)b * 64 + ci) * HH + h) * WW + wsrc];
        __half s0, s1;
        split2(v, s0, s1);
        size_t base = (((size_t)b * 256 + h) * 258 + w) * 64 + ci;
        g_xp[base] = s0;
        g_xp[base + XPLANE] = s1;
    }
}

template <int CIN>
__global__ void prep_w(const float* __restrict__ w, __half* __restrict__ dst) {
    const int NCC = CIN / 64;
    const size_t WPLANE = (size_t)256 * CIN * 9;
    int gid = blockIdx.x * 256 + threadIdx.x;
    if (gid >= (int)WPLANE) return;
    int tap = gid % 9, r = gid / 9;
    int ci = r % CIN, co = r / CIN;
    int dr = tap / 3, dc = tap % 3;
    int cic = ci >> 6, cj = ci & 63;
    int chunk = (dr * NCC + cic) * 3 + dc;
    size_t di = ((size_t)chunk * 256 + co) * 64 + cj;
    __half s0, s1;
    split2(w[gid], s0, s1);
    dst[di] = s0;
    dst[di + WPLANE] = s1;
}

// ===================== conv via mma.sync (fp16 2-split, 3 products) =====================
// grid (4 = 2 pxHalf x 2 coHalf, 256 h, 4 b), 256 threads (8 warps: 4M x 2N).
template <int CIN, bool SPLIT_OUT>
__global__ __launch_bounds__(256) void conv_mma(
    const __half* __restrict__ xp,   // [s][b][h][258][CIN]
    const __half* __restrict__ wsp,  // [s][chunk][256][64]
    const float* __restrict__ bias,
    __half* __restrict__ out_split,  // [s][b][h][258][256]
    float* __restrict__ out_planar)  // [b][co][h][w]
{
    constexpr int NCC = CIN / 64;
    constexpr int NCH = 9 * NCC;
    const size_t IPLANE = (size_t)4 * 256 * 258 * CIN;
    const size_t WPLANE = (size_t)NCH * 16384;
    const size_t OPLANE = (size_t)4 * 256 * 258 * 256;
    constexpr uint32_t BUFB = 65536;  // 32KB A + 32KB B per buffer

    extern __shared__ char smem_raw[];
    const uint32_t abase = (smem_u32(smem_raw) + 1023u) & ~1023u;

    const int tid = threadIdx.x;
    const int wid = tid >> 5, lane = tid & 31;
    const int warpM = wid & 3, warpN = wid >> 2;
    const int h = blockIdx.y, b = blockIdx.z;
    const int pxBase = (blockIdx.x & 1) * 128;
    const int coBase = (blockIdx.x >> 1) * 128;

    auto stage = [&](int chunk, int buf) {
        int dc = chunk % 3;
        int rem = chunk / 3;
        int cic = rem % NCC;
        int dr = rem / NCC;
        int hr = min(max(h + dr - 1, 0), HH - 1);
        const __half* xrow =
            xp + (((size_t)b * 256 + hr) * 258 + pxBase + dc) * CIN + cic * 64;
        uint32_t aoff = abase + buf * BUFB;
        uint32_t boff = aoff + 32768;
#pragma unroll
        for (int t = 0; t < 8; ++t) {
            int idx = tid + (t << 8);
            int plane = idx >> 10, r = idx & 1023;
            int px = r >> 3, seg = r & 7;
            const void* src = xrow + (size_t)plane * IPLANE + (size_t)px * CIN + seg * 8;
            cp_async16(aoff + plane * 16384 + swz128((px << 7) | (seg << 4)), src);
        }
        const __half* wrow = wsp + ((size_t)chunk * 256 + coBase) * 64;
#pragma unroll
        for (int t = 0; t < 8; ++t) {
            int idx = tid + (t << 8);
            int plane = idx >> 10, r = idx & 1023;
            int co = r >> 3, seg = r & 7;
            const void* src = wrow + (size_t)plane * WPLANE + (size_t)co * 64 + seg * 8;
            cp_async16(boff + plane * 16384 + swz128((co << 7) | (seg << 4)), src);
        }
        CP_COMMIT();
    };

    float acc[2][8][4];
#pragma unroll
    for (int mt = 0; mt < 2; ++mt)
#pragma unroll
        for (int nt = 0; nt < 8; ++nt)
#pragma unroll
            for (int e = 0; e < 4; ++e) acc[mt][nt][e] = 0.f;

    const uint32_t rA = lane & 15, cA = (lane >> 4) << 4;
    const uint32_t rB = (lane & 7) | ((lane >> 4) << 3), cB = ((lane >> 3) & 1) << 4;

    // products: (a0,b0), (a0,b1), (a1,b0)
    const int SA[3] = {0, 0, 1};
    const int SB[3] = {0, 1, 0};

    stage(0, 0);
    if (NCH > 1) stage(1, 1);

    for (int c = 0; c < NCH; ++c) {
        if (c + 1 < NCH) { CP_WAIT(1); } else { CP_WAIT(0); }
        __syncthreads();

        const int buf = c & 1;
        const uint32_t aB = abase + buf * BUFB;
        const uint32_t bB = aB + 32768;

        for (int ks = 0; ks < 4; ++ks) {
            uint32_t af[2][2][4];
#pragma unroll
            for (int plane = 0; plane < 2; ++plane)
#pragma unroll
                for (int mt = 0; mt < 2; ++mt) {
                    uint32_t row = warpM * 32 + mt * 16 + rA;
                    uint32_t addr = aB + plane * 16384 + swz128((row << 7) + ks * 32 + cA);
                    LDSM_X4(af[plane][mt][0], af[plane][mt][1], af[plane][mt][2],
                            af[plane][mt][3], addr);
                }
#pragma unroll
            for (int np = 0; np < 4; ++np) {
                uint32_t bfr[2][4];
#pragma unroll
                for (int plane = 0; plane < 2; ++plane) {
                    uint32_t row = warpN * 64 + np * 16 + rB;
                    uint32_t addr = bB + plane * 16384 + swz128((row << 7) + ks * 32 + cB);
                    LDSM_X4(bfr[plane][0], bfr[plane][1], bfr[plane][2], bfr[plane][3], addr);
                }
#pragma unroll
                for (int t = 0; t < 3; ++t) {
                    const int sa = SA[t], sb = SB[t];
#pragma unroll
                    for (int mt = 0; mt < 2; ++mt) {
                        MMA16816(acc[mt][2 * np], af[sa][mt], bfr[sb][0], bfr[sb][1]);
                        MMA16816(acc[mt][2 * np + 1], af[sa][mt], bfr[sb][2], bfr[sb][3]);
                    }
                }
            }
        }
        __syncthreads();
        if (c + 2 < NCH) stage(c + 2, buf);
    }

    // ---- epilogue ----
    float bv0[8], bv1[8];
#pragma unroll
    for (int nt = 0; nt < 8; ++nt) {
        int c0 = coBase + warpN * 64 + nt * 8 + (lane & 3) * 2;
        bv0[nt] = __ldg(bias + c0);
        bv1[nt] = __ldg(bias + c0 + 1);
    }

#pragma unroll
    for (int mt = 0; mt < 2; ++mt) {
#pragma unroll
        for (int nt = 0; nt < 8; ++nt) {
            int px0 = pxBase + warpM * 32 + mt * 16 + (lane >> 2);
            int c0 = coBase + warpN * 64 + nt * 8 + (lane & 3) * 2;
#pragma unroll
            for (int half = 0; half < 2; ++half) {
                int px = px0 + half * 8;
                float v0 = fmaxf(acc[mt][nt][2 * half] + bv0[nt], 0.f);
                float v1 = fmaxf(acc[mt][nt][2 * half + 1] + bv1[nt], 0.f);
                if (SPLIT_OUT) {
                    __half a0, a1, d0, d1;
                    split2(v0, a0, a1);
                    split2(v1, d0, d1);
                    uint32_t p0 = packh(a0, d0), p1 = packh(a1, d1);
                    size_t base = (((size_t)b * 256 + h) * 258 + px + 1) * 256 + c0;
                    *reinterpret_cast<uint32_t*>(out_split + base) = p0;
                    *reinterpret_cast<uint32_t*>(out_split + OPLANE + base) = p1;
                    if (px == 0 || px == 255) {
                        size_t hb =
                            (((size_t)b * 256 + h) * 258 + (px == 0 ? 0 : 257)) * 256 + c0;
                        *reinterpret_cast<uint32_t*>(out_split + hb) = p0;
                        *reinterpret_cast<uint32_t*>(out_split + OPLANE + hb) = p1;
                    }
                } else {
                    size_t o0 = ((size_t)b * 256 + c0) * HWTOT + h * WW + px;
                    out_planar[o0] = v0;
                    out_planar[o0 + HWTOT] = v1;
                }
            }
        }
    }
}

// ===================== fused 1x1 conv + cluster softmax head =====================
__global__ __launch_bounds__(256, 2) void head_kernel(
    const float* __restrict__ b3, const float* __restrict__ label, float* __restrict__ out)
{
    __shared__ __align__(16) float ws[16][256];
    __shared__ __align__(16) float bs[16][64];
    __shared__ __align__(16) float m2s[256][16];
    __shared__ float mu2s[16], c0s[16], labs[16];

    const int tid = threadIdx.x;
    const int tx = tid & 31, ty = tid >> 5;
    const int hw0 = blockIdx.x * 64;
    const int b = blockIdx.y;
    const float* q2b = g_q2 + (size_t)b * 256 * HWTOT;
    const int kk = tx & 15;

    for (int i = tid; i < 4096; i += 256) m2s[i >> 4][i & 15] = g_M2t[i];
    if (tid < 16) {
        mu2s[tid] = g_mu2[tid];
        c0s[tid] = g_c0[tid];
        labs[tid] = label[tid];
    }

    float acc[8][8];
    float crp[8];
#pragma unroll
    for (int pi = 0; pi < 8; ++pi) {
        crp[pi] = 0.f;
#pragma unroll
        for (int ci = 0; ci < 8; ++ci) acc[pi][ci] = 0.f;
    }

    for (int c0 = 0; c0 < 256; c0 += 16) {
        __syncthreads();
#pragma unroll
        for (int m = 0; m < 4; ++m) {
            int v = tid + m * 256;
            int s = v >> 6;
            int co = (v & 63) << 2;
            *(float4*)&ws[s][co] = *(const float4*)&g_w3t[(c0 + s) * 256 + co];
        }
        {
            int s = tid >> 4, p = (tid & 15) << 2;
            *(float4*)&bs[s][p] = *(const float4*)&q2b[(size_t)(c0 + s) * HWTOT + hw0 + p];
        }
        __syncthreads();
#pragma unroll
        for (int s = 0; s < 16; ++s) {
            float4 a0 = *(const float4*)&bs[s][ty * 4];
            float4 a1 = *(const float4*)&bs[s][32 + ty * 4];
            float4 w0v = *(const float4*)&ws[s][tx * 4];
            float4 w1v = *(const float4*)&ws[s][128 + tx * 4];
            float av[8] = {a0.x, a0.y, a0.z, a0.w, a1.x, a1.y, a1.z, a1.w};
            float wv[8] = {w0v.x, w0v.y, w0v.z, w0v.w, w1v.x, w1v.y, w1v.z, w1v.w};
            float m2v = m2s[c0 + s][kk];
#pragma unroll
            for (int pi = 0; pi < 8; ++pi) {
#pragma unroll
                for (int ci = 0; ci < 8; ++ci) acc[pi][ci] = fmaf(av[pi], wv[ci], acc[pi][ci]);
                crp[pi] = fmaf(av[pi], m2v, crp[pi]);
            }
        }
    }

    float4 bb0 = *(const float4*)&b3[tx * 4];
    float4 bb1 = *(const float4*)&b3[128 + tx * 4];
    float bc[8] = {bb0.x, bb0.y, bb0.z, bb0.w, bb1.x, bb1.y, bb1.z, bb1.w};

#pragma unroll
    for (int pi = 0; pi < 8; ++pi) {
        float s2 = 0.f;
#pragma unroll
        for (int ci = 0; ci < 8; ++ci) {
            float q = acc[pi][ci] + bc[ci];
            s2 = fmaf(q, q, s2);
        }
#pragma unroll
        for (int off = 16; off; off >>= 1) s2 += __shfl_xor_sync(0xffffffffu, s2, off);

        float cr = crp[pi] + c0s[kk];
        float logit = 2.f * cr - s2 - mu2s[kk];

        float mx = logit;
#pragma unroll
        for (int off = 8; off; off >>= 1)
            mx = fmaxf(mx, __shfl_xor_sync(0xffffffffu, mx, off));
        float e = __expf(logit - mx);
        float se = e, sl = e * labs[kk];
#pragma unroll
        for (int off = 8; off; off >>= 1) {
            se += __shfl_xor_sync(0xffffffffu, se, off);
            sl += __shfl_xor_sync(0xffffffffu, sl, off);
        }
        if (tx == 0) {
            int p = (pi < 4) ? (ty * 4 + pi) : (32 + ty * 4 + (pi - 4));
            out[(size_t)b * HWTOT + hw0 + p] = sl / se;
        }
    }
}

// ===================== launch =====================
extern "C" void kernel_launch(void* const* d_in, const int* in_sizes, int n_in,
                              void* d_out, int out_size) {
    const float* x = (const float*)d_in[0];
    const float* w1 = (const float*)d_in[1];
    const float* b1 = (const float*)d_in[2];
    const float* w2 = (const float*)d_in[3];
    const float* b2 = (const float*)d_in[4];
    const float* w3 = (const float*)d_in[5];
    const float* b3 = (const float*)d_in[6];
    const float* mu = (const float*)d_in[7];
    const float* label = (const float*)d_in[8];
    float* out = (float*)d_out;

    __half *xp, *q1p, *w1s, *w2s;
    float* q2;
    cudaGetSymbolAddress((void**)&xp, g_xp);
    cudaGetSymbolAddress((void**)&q1p, g_q1p);
    cudaGetSymbolAddress((void**)&q2, g_q2);
    cudaGetSymbolAddress((void**)&w1s, g_w1s);
    cudaGetSymbolAddress((void**)&w2s, g_w2s);

    const int SMEM_BYTES = 2 * 65536 + 1024;
    cudaFuncSetAttribute(conv_mma<64, true>, cudaFuncAttributeMaxDynamicSharedMemorySize,
                         SMEM_BYTES);
    cudaFuncSetAttribute(conv_mma<256, false>, cudaFuncAttributeMaxDynamicSharedMemorySize,
                         SMEM_BYTES);

    prep_head<<<1, 256>>>(w3, b3, mu);
    prep_x<<<dim3(256, 4), 256>>>(x);
    prep_w<64><<<576, 256>>>(w1, w1s);
    prep_w<256><<<2304, 256>>>(w2, w2s);

    dim3 cgrid(4, 256, 4);
    conv_mma<64, true><<<cgrid, 256, SMEM_BYTES>>>(xp, w1s, b1, q1p, nullptr);
    conv_mma<256, false><<<cgrid, 256, SMEM_BYTES>>>(q1p, w2s, b2, nullptr, q2);

    head_kernel<<<dim3(1024, 4), 256>>>(b3, label, out);
}

// round 5
// speedup vs baseline: 3.3972x; 1.2335x over previous
#include <cuda_runtime.h>
#include <cuda_fp16.h>
#include <cstdint>
#include <math.h>

#define HH 256
#define WW 256
#define HWTOT 65536

// ===================== device scratch =====================
__device__ __align__(256) __half g_xp[33816576];    // 2 * 4*256*258*64   [s][b][h][w0..257][ci]
__device__ __align__(256) __half g_q1p[135266304];  // 2 * 4*256*258*256
__device__ __align__(256) float  g_q2[67108864];    // planar (4,256,256,256)
__device__ __align__(256) __half g_w1s[294912];     // 2 * 9*256*64   [s][chunk][co][ci64]
__device__ __align__(256) __half g_w2s[1179648];    // 2 * 36*256*64
__device__ float g_M2t[256 * 16];   // M2t[ci][k] = sum_co mu[k][co]*w3[co][ci]
__device__ float g_c0[16];
__device__ float g_mu2[16];

// ===================== helpers =====================
__device__ __forceinline__ uint32_t smem_u32(const void* p) {
    uint32_t a;
    asm("{ .reg .u64 t; cvta.to.shared.u64 t, %1; cvt.u32.u64 %0, t; }" : "=r"(a) : "l"(p));
    return a;
}
__device__ __forceinline__ uint32_t swz128(uint32_t o) { return o ^ ((o >> 3) & 0x70); }

__device__ __forceinline__ void cp_async16(uint32_t dst, const void* src) {
    asm volatile("cp.async.cg.shared.global [%0], [%1], 16;" :: "r"(dst), "l"(src) : "memory");
}
#define CP_COMMIT() asm volatile("cp.async.commit_group;" ::: "memory")
#define CP_WAIT(n)  asm volatile("cp.async.wait_group %0;" :: "n"(n) : "memory")

#define LDSM_X4(r0, r1, r2, r3, addr) \
    asm volatile("ldmatrix.sync.aligned.m8n8.x4.shared.b16 {%0,%1,%2,%3}, [%4];" \
                 : "=r"(r0), "=r"(r1), "=r"(r2), "=r"(r3) : "r"(addr))

#define MMA16816(d, a, b0, b1) \
    asm volatile("mma.sync.aligned.m16n8k16.row.col.f32.f16.f16.f32 " \
                 "{%0,%1,%2,%3}, {%4,%5,%6,%7}, {%8,%9}, {%0,%1,%2,%3};" \
                 : "+f"((d)[0]), "+f"((d)[1]), "+f"((d)[2]), "+f"((d)[3]) \
                 : "r"((a)[0]), "r"((a)[1]), "r"((a)[2]), "r"((a)[3]), "r"(b0), "r"(b1))

__device__ __forceinline__ void split2(float v, __half& h0, __half& h1) {
    h0 = __float2half_rn(v);
    float r = v - __half2float(h0);
    h1 = __float2half_rn(r);
}
__device__ __forceinline__ uint32_t packh(__half lo, __half hi) {
    unsigned short a = *reinterpret_cast<unsigned short*>(&lo);
    unsigned short b = *reinterpret_cast<unsigned short*>(&hi);
    return (uint32_t)a | ((uint32_t)b << 16);
}

// ===================== prep kernels =====================
__global__ void prep_head(const float* __restrict__ w3, const float* __restrict__ b3,
                          const float* __restrict__ mu) {
    const int tid = threadIdx.x;
    for (int p = tid; p < 4096; p += 256) {
        int ci = p >> 4, k = p & 15;
        float s = 0.f;
        for (int co = 0; co < 256; ++co) s = fmaf(mu[k * 256 + co], w3[co * 256 + ci], s);
        g_M2t[ci * 16 + k] = s;
    }
    if (tid < 16) {
        float s = 0.f, m2 = 0.f;
        for (int c = 0; c < 256; ++c) {
            float mv = mu[tid * 256 + c];
            s = fmaf(mv, b3[c], s);
            m2 = fmaf(mv, mv, m2);
        }
        g_c0[tid] = s;
        g_mu2[tid] = m2;
    }
}

__global__ void prep_x(const float* __restrict__ x) {
    const int h = blockIdx.x, b = blockIdx.y, tid = threadIdx.x;
    const size_t XPLANE = 16908288;  // 4*256*258*64
    for (int idx = tid; idx < 258 * 64; idx += 256) {
        int w = idx >> 6, ci = idx & 63;
        int wsrc = min(max(w - 1, 0), WW - 1);
        float v = x[(((size_t)b * 64 + ci) * HH + h) * WW + wsrc];
        __half s0, s1;
        split2(v, s0, s1);
        size_t base = (((size_t)b * 256 + h) * 258 + w) * 64 + ci;
        g_xp[base] = s0;
        g_xp[base + XPLANE] = s1;
    }
}

template <int CIN>
__global__ void prep_w(const float* __restrict__ w, __half* __restrict__ dst) {
    const int NCC = CIN / 64;
    const size_t WPLANE = (size_t)256 * CIN * 9;
    int gid = blockIdx.x * 256 + threadIdx.x;
    if (gid >= (int)WPLANE) return;
    int tap = gid % 9, r = gid / 9;
    int ci = r % CIN, co = r / CIN;
    int dr = tap / 3, dc = tap % 3;
    int cic = ci >> 6, cj = ci & 63;
    int chunk = (dr * NCC + cic) * 3 + dc;
    size_t di = ((size_t)chunk * 256 + co) * 64 + cj;
    __half s0, s1;
    split2(w[gid], s0, s1);
    dst[di] = s0;
    dst[di + WPLANE] = s1;
}

// ===================== conv via mma.sync (fp16 2-split, 3 products) =====================
// grid (4 = 2 pxHalf x 2 coHalf, 256 h, 4 b), 256 threads (8 warps: 4M x 2N).
// 3-buffer cp.async ring, ONE __syncthreads per K-chunk.
template <int CIN, bool SPLIT_OUT>
__global__ __launch_bounds__(256) void conv_mma(
    const __half* __restrict__ xp,   // [s][b][h][258][CIN]
    const __half* __restrict__ wsp,  // [s][chunk][256][64]
    const float* __restrict__ bias,
    __half* __restrict__ out_split,  // [s][b][h][258][256]
    float* __restrict__ out_planar)  // [b][co][h][w]
{
    constexpr int NCC = CIN / 64;
    constexpr int NCH = 9 * NCC;
    const size_t IPLANE = (size_t)4 * 256 * 258 * CIN;
    const size_t WPLANE = (size_t)NCH * 16384;
    const size_t OPLANE = (size_t)4 * 256 * 258 * 256;
    constexpr uint32_t BUFB = 65536;  // 32KB A + 32KB B per buffer

    extern __shared__ char smem_raw[];
    const uint32_t abase = (smem_u32(smem_raw) + 1023u) & ~1023u;

    const int tid = threadIdx.x;
    const int wid = tid >> 5, lane = tid & 31;
    const int warpM = wid & 3, warpN = wid >> 2;
    const int h = blockIdx.y, b = blockIdx.z;
    const int pxBase = (blockIdx.x & 1) * 128;
    const int coBase = (blockIdx.x >> 1) * 128;

    auto stage = [&](int chunk, int buf) {
        int dc = chunk % 3;
        int rem = chunk / 3;
        int cic = rem % NCC;
        int dr = rem / NCC;
        int hr = min(max(h + dr - 1, 0), HH - 1);
        const __half* xrow =
            xp + (((size_t)b * 256 + hr) * 258 + pxBase + dc) * CIN + cic * 64;
        uint32_t aoff = abase + buf * BUFB;
        uint32_t boff = aoff + 32768;
#pragma unroll
        for (int t = 0; t < 8; ++t) {
            int idx = tid + (t << 8);
            int plane = idx >> 10, r = idx & 1023;
            int px = r >> 3, seg = r & 7;
            const void* src = xrow + (size_t)plane * IPLANE + (size_t)px * CIN + seg * 8;
            cp_async16(aoff + plane * 16384 + swz128((px << 7) | (seg << 4)), src);
        }
        const __half* wrow = wsp + ((size_t)chunk * 256 + coBase) * 64;
#pragma unroll
        for (int t = 0; t < 8; ++t) {
            int idx = tid + (t << 8);
            int plane = idx >> 10, r = idx & 1023;
            int co = r >> 3, seg = r & 7;
            const void* src = wrow + (size_t)plane * WPLANE + (size_t)co * 64 + seg * 8;
            cp_async16(boff + plane * 16384 + swz128((co << 7) | (seg << 4)), src);
        }
        CP_COMMIT();
    };

    float acc[2][8][4];
#pragma unroll
    for (int mt = 0; mt < 2; ++mt)
#pragma unroll
        for (int nt = 0; nt < 8; ++nt)
#pragma unroll
            for (int e = 0; e < 4; ++e) acc[mt][nt][e] = 0.f;

    const uint32_t rA = lane & 15, cA = (lane >> 4) << 4;
    const uint32_t rB = (lane & 7) | ((lane >> 4) << 3), cB = ((lane >> 3) & 1) << 4;

    // products: (a0,b0), (a0,b1), (a1,b0)
    const int SA[3] = {0, 0, 1};
    const int SB[3] = {0, 1, 0};

    int mod3 = 2;  // (c+2)%3 tracker
    stage(0, 0);
    if (NCH > 1) stage(1, 1);

    for (int c = 0; c < NCH; ++c) {
        if (c + 1 < NCH) { CP_WAIT(1); } else { CP_WAIT(0); }
        __syncthreads();
        if (c + 2 < NCH) stage(c + 2, mod3);

        const int buf = c - (c / 3) * 3;  // c % 3
        mod3 = buf;                        // next iteration's (c+2)%3 == c%3
        const uint32_t aB = abase + (uint32_t)buf * BUFB;
        const uint32_t bB = aB + 32768;

        for (int ks = 0; ks < 4; ++ks) {
            uint32_t af[2][2][4];
#pragma unroll
            for (int plane = 0; plane < 2; ++plane)
#pragma unroll
                for (int mt = 0; mt < 2; ++mt) {
                    uint32_t row = warpM * 32 + mt * 16 + rA;
                    uint32_t addr = aB + plane * 16384 + swz128((row << 7) + ks * 32 + cA);
                    LDSM_X4(af[plane][mt][0], af[plane][mt][1], af[plane][mt][2],
                            af[plane][mt][3], addr);
                }
#pragma unroll
            for (int np = 0; np < 4; ++np) {
                uint32_t bfr[2][4];
#pragma unroll
                for (int plane = 0; plane < 2; ++plane) {
                    uint32_t row = warpN * 64 + np * 16 + rB;
                    uint32_t addr = bB + plane * 16384 + swz128((row << 7) + ks * 32 + cB);
                    LDSM_X4(bfr[plane][0], bfr[plane][1], bfr[plane][2], bfr[plane][3], addr);
                }
#pragma unroll
                for (int t = 0; t < 3; ++t) {
                    const int sa = SA[t], sb = SB[t];
#pragma unroll
                    for (int mt = 0; mt < 2; ++mt) {
                        MMA16816(acc[mt][2 * np], af[sa][mt], bfr[sb][0], bfr[sb][1]);
                        MMA16816(acc[mt][2 * np + 1], af[sa][mt], bfr[sb][2], bfr[sb][3]);
                    }
                }
            }
        }
    }

    // ---- epilogue ----
    float bv0[8], bv1[8];
#pragma unroll
    for (int nt = 0; nt < 8; ++nt) {
        int c0 = coBase + warpN * 64 + nt * 8 + (lane & 3) * 2;
        bv0[nt] = __ldg(bias + c0);
        bv1[nt] = __ldg(bias + c0 + 1);
    }

#pragma unroll
    for (int mt = 0; mt < 2; ++mt) {
#pragma unroll
        for (int nt = 0; nt < 8; ++nt) {
            int px0 = pxBase + warpM * 32 + mt * 16 + (lane >> 2);
            int c0 = coBase + warpN * 64 + nt * 8 + (lane & 3) * 2;
#pragma unroll
            for (int half = 0; half < 2; ++half) {
                int px = px0 + half * 8;
                float v0 = fmaxf(acc[mt][nt][2 * half] + bv0[nt], 0.f);
                float v1 = fmaxf(acc[mt][nt][2 * half + 1] + bv1[nt], 0.f);
                if (SPLIT_OUT) {
                    __half a0, a1, d0, d1;
                    split2(v0, a0, a1);
                    split2(v1, d0, d1);
                    uint32_t p0 = packh(a0, d0), p1 = packh(a1, d1);
                    size_t base = (((size_t)b * 256 + h) * 258 + px + 1) * 256 + c0;
                    *reinterpret_cast<uint32_t*>(out_split + base) = p0;
                    *reinterpret_cast<uint32_t*>(out_split + OPLANE + base) = p1;
                    if (px == 0 || px == 255) {
                        size_t hb =
                            (((size_t)b * 256 + h) * 258 + (px == 0 ? 0 : 257)) * 256 + c0;
                        *reinterpret_cast<uint32_t*>(out_split + hb) = p0;
                        *reinterpret_cast<uint32_t*>(out_split + OPLANE + hb) = p1;
                    }
                } else {
                    size_t o0 = ((size_t)b * 256 + c0) * HWTOT + h * WW + px;
                    out_planar[o0] = v0;
                    out_planar[o0 + HWTOT] = v1;
                }
            }
        }
    }
}

// ===================== head: cross-only + softmax (s2 cancels in softmax) =====================
// logit~[k] = 2*(cross[k] + c0[k]) - mu2[k]; softmax over k; dot with label.
// grid (128, 4), 256 threads, 2 px per thread (float2 coalesced).
__global__ __launch_bounds__(256) void cross_head(
    const float* __restrict__ label, float* __restrict__ out)
{
    __shared__ __align__(16) float m2s[256][16];
    __shared__ float c2s[16], labs[16];

    const int tid = threadIdx.x;
    const int b = blockIdx.y;
    const int px0 = blockIdx.x * 512 + tid * 2;

    for (int i = tid; i < 4096; i += 256) m2s[i >> 4][i & 15] = g_M2t[i];
    if (tid < 16) {
        c2s[tid] = 2.f * g_c0[tid] - g_mu2[tid];
        labs[tid] = label[tid];
    }
    __syncthreads();

    const float* q2b = g_q2 + (size_t)b * 256 * HWTOT + px0;

    float acc[16][2];
#pragma unroll
    for (int k = 0; k < 16; ++k) acc[k][0] = acc[k][1] = 0.f;

#pragma unroll 4
    for (int ci = 0; ci < 256; ++ci) {
        float2 v = *reinterpret_cast<const float2*>(q2b + (size_t)ci * HWTOT);
        float4 m0 = *reinterpret_cast<const float4*>(&m2s[ci][0]);
        float4 m1 = *reinterpret_cast<const float4*>(&m2s[ci][4]);
        float4 m2v = *reinterpret_cast<const float4*>(&m2s[ci][8]);
        float4 m3 = *reinterpret_cast<const float4*>(&m2s[ci][12]);
        float mm[16] = {m0.x, m0.y, m0.z, m0.w, m1.x, m1.y, m1.z, m1.w,
                        m2v.x, m2v.y, m2v.z, m2v.w, m3.x, m3.y, m3.z, m3.w};
#pragma unroll
        for (int k = 0; k < 16; ++k) {
            acc[k][0] = fmaf(v.x, mm[k], acc[k][0]);
            acc[k][1] = fmaf(v.y, mm[k], acc[k][1]);
        }
    }

#pragma unroll
    for (int j = 0; j < 2; ++j) {
        float lg[16];
        float mx = -1e30f;
#pragma unroll
        for (int k = 0; k < 16; ++k) {
            lg[k] = fmaf(2.f, acc[k][j], c2s[k]);
            mx = fmaxf(mx, lg[k]);
        }
        float se = 0.f, sl = 0.f;
#pragma unroll
        for (int k = 0; k < 16; ++k) {
            float e = __expf(lg[k] - mx);
            se += e;
            sl = fmaf(e, labs[k], sl);
        }
        out[(size_t)b * HWTOT + px0 + j] = sl / se;
    }
}

// ===================== launch =====================
extern "C" void kernel_launch(void* const* d_in, const int* in_sizes, int n_in,
                              void* d_out, int out_size) {
    const float* x = (const float*)d_in[0];
    const float* w1 = (const float*)d_in[1];
    const float* b1 = (const float*)d_in[2];
    const float* w2 = (const float*)d_in[3];
    const float* b2 = (const float*)d_in[4];
    const float* w3 = (const float*)d_in[5];
    const float* b3 = (const float*)d_in[6];
    const float* mu = (const float*)d_in[7];
    const float* label = (const float*)d_in[8];
    float* out = (float*)d_out;

    __half *xp, *q1p, *w1s, *w2s;
    float* q2;
    cudaGetSymbolAddress((void**)&xp, g_xp);
    cudaGetSymbolAddress((void**)&q1p, g_q1p);
    cudaGetSymbolAddress((void**)&q2, g_q2);
    cudaGetSymbolAddress((void**)&w1s, g_w1s);
    cudaGetSymbolAddress((void**)&w2s, g_w2s);

    const int SMEM_BYTES = 3 * 65536 + 1024;
    cudaFuncSetAttribute(conv_mma<64, true>, cudaFuncAttributeMaxDynamicSharedMemorySize,
                         SMEM_BYTES);
    cudaFuncSetAttribute(conv_mma<256, false>, cudaFuncAttributeMaxDynamicSharedMemorySize,
                         SMEM_BYTES);

    prep_head<<<1, 256>>>(w3, b3, mu);
    prep_x<<<dim3(256, 4), 256>>>(x);
    prep_w<64><<<576, 256>>>(w1, w1s);
    prep_w<256><<<2304, 256>>>(w2, w2s);

    dim3 cgrid(4, 256, 4);
    conv_mma<64, true><<<cgrid, 256, SMEM_BYTES>>>(xp, w1s, b1, q1p, nullptr);
    conv_mma<256, false><<<cgrid, 256, SMEM_BYTES>>>(q1p, w2s, b2, nullptr, q2);

    cross_head<<<dim3(128, 4), 256>>>(label, out);
}